// round 17
// baseline (speedup 1.0000x reference)
#include <cuda_runtime.h>
#include <math.h>

#define NMAX 50000
#define EMAX 600000
#define HDIM 128
#define NHEADS 4
#define GMAX 64
#define NTILES_PAD 3128

// ---------------- scratch (device globals; no allocation) ----------------
__device__ float d_h[NMAX * HDIM];
__device__ float d_feat[NMAX * HDIM];
__device__ float d_el[NMAX * NHEADS];
__device__ float d_er[NMAX * NHEADS];
__device__ float d_elmax[3 * NHEADS];
__device__ int   d_deg[NMAX];
__device__ int   d_offs[NMAX + 1];
__device__ int   d_esrc[EMAX];
__device__ int   d_bsum[64];
__device__ int   d_bbase[64];
__device__ float d_gz[GMAX];
__device__ float d_zg[GMAX * HDIM];
__device__ unsigned int d_Afrag[NTILES_PAD * 8 * 32 * 8];   // [tile][chunk][lane][hi4|lo4]
__device__ unsigned int d_Bfrag[3 * 128 * 32 * 4];          // [l][chunk*16+j][lane][bh0,bh1,bl0,bl1]

// ---------------- helpers ----------------
__device__ __forceinline__ void atomicMaxFloat(float* addr, float v) {
    if (v >= 0.0f) atomicMax((int*)addr, __float_as_int(v));
    else           atomicMin((unsigned int*)addr, __float_as_uint(v));
}

__device__ __forceinline__ void redAdd4(float* p, float a, float b, float c, float d) {
    asm volatile("red.global.add.v4.f32 [%0], {%1, %2, %3, %4};"
                 :: "l"(p), "f"(a), "f"(b), "f"(c), "f"(d) : "memory");
}

__device__ __forceinline__ float warpSum(float v) {
    #pragma unroll
    for (int o = 16; o > 0; o >>= 1) v += __shfl_xor_sync(0xffffffffu, v, o);
    return v;
}

__device__ __forceinline__ unsigned int pack_bf16x2(float x1, float x0) {
    unsigned int r;
    asm("cvt.rn.bf16x2.f32 %0, %1, %2;" : "=r"(r) : "f"(x1), "f"(x0));
    return r;
}
__device__ __forceinline__ float bf16lo_f(unsigned int p) { return __uint_as_float(p << 16); }
__device__ __forceinline__ float bf16hi_f(unsigned int p) { return __uint_as_float(p & 0xffff0000u); }

__device__ __forceinline__ void bf16_split_pair(float x0, float x1,
                                                unsigned int& hp, unsigned int& lp) {
    hp = pack_bf16x2(x1, x0);
    float f0 = bf16lo_f(hp), f1 = bf16hi_f(hp);
    lp = pack_bf16x2(x1 - f1, x0 - f0);
}

#define MMA_BF16(c, a0, a1, a2, a3, b0, b1)                                             \
    asm("mma.sync.aligned.m16n8k16.row.col.f32.bf16.bf16.f32 "                          \
        "{%0,%1,%2,%3}, {%4,%5,%6,%7}, {%8,%9}, {%0,%1,%2,%3};"                         \
        : "+f"((c)[0]), "+f"((c)[1]), "+f"((c)[2]), "+f"((c)[3])                        \
        : "r"(a0), "r"(a1), "r"(a2), "r"(a3), "r"(b0), "r"(b1))

// ---------------- kernels ----------------

__global__ void csr_zero_k(int n) {
    int i = blockIdx.x * blockDim.x + threadIdx.x;
    if (i < n) d_deg[i] = 0;
    if (i < 3 * NHEADS) d_elmax[i] = -1e30f;
    if (i < GMAX * HDIM) d_zg[i] = 0.0f;
    if (i < GMAX) d_gz[i] = 0.0f;
}

__global__ void csr_hist_k(const int* __restrict__ dst, int e) {
    int i = blockIdx.x * blockDim.x + threadIdx.x;
    if (i < e) atomicAdd(&d_deg[dst[i]], 1);
}

__global__ void csr_scan1_k(int n) {
    __shared__ int wsum[32];
    int i = blockIdx.x * 1024 + threadIdx.x;
    int lane = threadIdx.x & 31, wid = threadIdx.x >> 5;
    int v = (i < n) ? d_deg[i] : 0;
    int x = v;
    #pragma unroll
    for (int o = 1; o < 32; o <<= 1) {
        int t = __shfl_up_sync(0xffffffffu, x, o);
        if (lane >= o) x += t;
    }
    if (lane == 31) wsum[wid] = x;
    __syncthreads();
    if (wid == 0) {
        int y = wsum[lane];
        #pragma unroll
        for (int o = 1; o < 32; o <<= 1) {
            int t = __shfl_up_sync(0xffffffffu, y, o);
            if (lane >= o) y += t;
        }
        wsum[lane] = y;
    }
    __syncthreads();
    int base = (wid > 0) ? wsum[wid - 1] : 0;
    if (i < n) d_offs[i] = base + x - v;
    if (threadIdx.x == 1023) d_bsum[blockIdx.x] = wsum[31];
}

__global__ void csr_scan2_k(int nb, int n) {
    int lane = threadIdx.x;
    int v0 = (lane < nb) ? d_bsum[lane] : 0;
    int v1 = (32 + lane < nb) ? d_bsum[32 + lane] : 0;
    int x0 = v0, x1 = v1;
    #pragma unroll
    for (int o = 1; o < 32; o <<= 1) {
        int t0 = __shfl_up_sync(0xffffffffu, x0, o);
        int t1 = __shfl_up_sync(0xffffffffu, x1, o);
        if (lane >= o) { x0 += t0; x1 += t1; }
    }
    int tot0 = __shfl_sync(0xffffffffu, x0, 31);
    int tot1 = __shfl_sync(0xffffffffu, x1, 31);
    if (lane < nb) d_bbase[lane] = x0 - v0;
    if (32 + lane < nb) d_bbase[32 + lane] = tot0 + x1 - v1;
    if (lane == 0) d_offs[n] = tot0 + tot1;
}

__global__ void csr_scan3_k(int n) {
    int i = blockIdx.x * 1024 + threadIdx.x;
    if (i < n) d_offs[i] += d_bbase[blockIdx.x];
}

// Destructive scatter: after this, d_offs[i] == end of node i's edge range.
__global__ void csr_scatter_k(const int* __restrict__ src, const int* __restrict__ dst, int e) {
    int i = blockIdx.x * blockDim.x + threadIdx.x;
    if (i >= e) return;
    int d = dst[i];
    int pos = atomicAdd(&d_offs[d], 1);
    d_esrc[pos] = src[i];
}

// Convert W[l] (3 layers) to fragment-major bf16 hi/lo. Runs once per call.
__global__ void convB_k(const float* __restrict__ W) {
    int idx = blockIdx.x * blockDim.x + threadIdx.x;
    if (idx >= 3 * 128 * 32) return;
    int lane = idx & 31;
    int jc = (idx >> 5) & 15;
    int ch = (idx >> 9) & 7;
    int l = idx >> 12;
    const float* B = W + l * HDIM * HDIM;
    int col = jc * 8 + (lane >> 2);
    int t4 = lane & 3;
    int kc = ch * 16;
    float b00 = B[(kc + 2 * t4) * HDIM + col];
    float b01 = B[(kc + 2 * t4 + 1) * HDIM + col];
    float b10 = B[(kc + 2 * t4 + 8) * HDIM + col];
    float b11 = B[(kc + 2 * t4 + 9) * HDIM + col];
    unsigned int bh0, bl0, bh1, bl1;
    bf16_split_pair(b00, b01, bh0, bl0);
    bf16_split_pair(b10, b11, bh1, bl1);
    *(uint4*)&d_Bfrag[((l * 128 + ch * 16 + jc) * 32 + lane) * 4] =
        make_uint4(bh0, bh1, bl0, bl1);
}

// Layer-0 only: embedding + fragment conversion.
__global__ void convA_k(int n, const int* __restrict__ gt, const int* __restrict__ qi,
                        const float* __restrict__ ge, const float* __restrict__ qe) {
    __shared__ float hs[128][20];
    int row0 = blockIdx.x * 128;
    int tid = threadIdx.x;
    int tile = tid >> 5, lane = tid & 31;
    int g = lane >> 2, t4 = lane & 3;
    int gmt = blockIdx.x * 8 + tile;
    for (int kc = 0; kc < HDIM; kc += 16) {
        #pragma unroll
        for (int it = 0; it < 2; it++) {
            int idx = tid + it * 256;
            int row = idx >> 2;
            int kq = (idx & 3) * 4;
            float4 v = make_float4(0.f, 0.f, 0.f, 0.f);
            int grow = row0 + row;
            if (grow < n) {
                int gg = gt[grow], qq = qi[grow];
                float4 a = *(const float4*)(ge + gg * HDIM + kc + kq);
                float4 b = *(const float4*)(qe + qq * HDIM + kc + kq);
                v.x = a.x + b.x; v.y = a.y + b.y; v.z = a.z + b.z; v.w = a.w + b.w;
                *(float4*)(d_h + grow * HDIM + kc + kq) = v;
            }
            hs[row][kq] = v.x; hs[row][kq + 1] = v.y;
            hs[row][kq + 2] = v.z; hs[row][kq + 3] = v.w;
        }
        __syncthreads();
        int r0 = tile * 16 + g, r1 = r0 + 8;
        unsigned int h0, l0_, h1, l1_, h2, l2_, h3, l3_;
        bf16_split_pair(hs[r0][2 * t4], hs[r0][2 * t4 + 1], h0, l0_);
        bf16_split_pair(hs[r1][2 * t4], hs[r1][2 * t4 + 1], h1, l1_);
        bf16_split_pair(hs[r0][2 * t4 + 8], hs[r0][2 * t4 + 9], h2, l2_);
        bf16_split_pair(hs[r1][2 * t4 + 8], hs[r1][2 * t4 + 9], h3, l3_);
        unsigned int* p = &d_Afrag[((gmt * 8 + (kc >> 4)) * 32 + lane) * 8];
        *(uint4*)p = make_uint4(h0, h1, h2, h3);
        *(uint4*)(p + 4) = make_uint4(l0_, l1_, l2_, l3_);
        __syncthreads();
    }
}

// feat = h @ W[l] via bf16-split MMA on pre-converted fragments.
// Col-split: warp = 16 rows x 64 cols (half the j-range) for 2x occupancy.
// Fused attn epilogue (el/er + global el-max); head h lives fully in one half.
__global__ void __launch_bounds__(256, 3)
gemm_attn_k(const float* __restrict__ al, const float* __restrict__ ar,
            int n, int l, int ntiles) {
    __shared__ float smax[NHEADS];
    int tid = threadIdx.x;
    if (tid < NHEADS) smax[tid] = -1e30f;
    __syncthreads();
    int w = tid >> 5;
    int lane = tid & 31;
    int gmt = blockIdx.x * 4 + (w >> 1);
    int jh = w & 1;                       // column half
    int g = lane >> 2, t4 = lane & 3;

    if (gmt < ntiles) {
        float c[8][4];
        #pragma unroll
        for (int j = 0; j < 8; j++)
            #pragma unroll
            for (int q = 0; q < 4; q++) c[j][q] = 0.0f;

        const unsigned int* ap = &d_Afrag[(gmt * 8 * 32 + lane) * 8];
        const unsigned int* bp = &d_Bfrag[(l * 128 * 32 + lane) * 4];
        #pragma unroll
        for (int ch = 0; ch < 8; ch++) {
            uint4 ah = __ldg((const uint4*)(ap + ch * 256));
            uint4 alo = __ldg((const uint4*)(ap + ch * 256 + 4));
            #pragma unroll
            for (int jj = 0; jj < 8; jj++) {
                int j = jh * 8 + jj;
                uint4 bf = __ldg((const uint4*)(bp + (ch * 16 + j) * 128));
                MMA_BF16(c[jj], ah.x, ah.y, ah.z, ah.w, bf.x, bf.y);
                MMA_BF16(c[jj], ah.x, ah.y, ah.z, ah.w, bf.z, bf.w);
                MMA_BF16(c[jj], alo.x, alo.y, alo.z, alo.w, bf.x, bf.y);
            }
        }

        int r0 = gmt * 16 + g;
        int r1 = r0 + 8;
        float elp0[2] = {0, 0}, elp1[2] = {0, 0};
        float erp0[2] = {0, 0}, erp1[2] = {0, 0};
        #pragma unroll
        for (int jj = 0; jj < 8; jj++) {
            int j = jh * 8 + jj;
            int col = j * 8 + 2 * t4;
            if (r0 < n) *(float2*)(d_feat + r0 * HDIM + col) = make_float2(c[jj][0], c[jj][1]);
            if (r1 < n) *(float2*)(d_feat + r1 * HDIM + col) = make_float2(c[jj][2], c[jj][3]);
            float2 alv = __ldg((const float2*)(al + col));
            float2 arv = __ldg((const float2*)(ar + col));
            int h = jj >> 2;              // 0..1 within this half
            elp0[h] += c[jj][0] * alv.x + c[jj][1] * alv.y;
            elp1[h] += c[jj][2] * alv.x + c[jj][3] * alv.y;
            erp0[h] += c[jj][0] * arv.x + c[jj][1] * arv.y;
            erp1[h] += c[jj][2] * arv.x + c[jj][3] * arv.y;
        }
        #pragma unroll
        for (int h = 0; h < 2; h++) {
            #pragma unroll
            for (int o = 1; o <= 2; o <<= 1) {
                elp0[h] += __shfl_xor_sync(0xffffffffu, elp0[h], o);
                elp1[h] += __shfl_xor_sync(0xffffffffu, elp1[h], o);
                erp0[h] += __shfl_xor_sync(0xffffffffu, erp0[h], o);
                erp1[h] += __shfl_xor_sync(0xffffffffu, erp1[h], o);
            }
        }
        if (t4 < 2) {
            int hd = jh * 2 + t4;
            float myelmax = -1e30f;
            if (r0 < n) {
                d_el[r0 * NHEADS + hd] = elp0[t4];
                d_er[r0 * NHEADS + hd] = erp0[t4];
                myelmax = fmaxf(myelmax, elp0[t4]);
            }
            if (r1 < n) {
                d_el[r1 * NHEADS + hd] = elp1[t4];
                d_er[r1 * NHEADS + hd] = erp1[t4];
                myelmax = fmaxf(myelmax, elp1[t4]);
            }
            atomicMaxFloat(&smax[hd], myelmax);
        }
    }
    __syncthreads();
    if (tid < NHEADS) atomicMaxFloat(&d_elmax[l * NHEADS + tid], smax[tid]);
}

// Fused per-layer GAT aggregation: 512 threads = 16 warps = 16 nodes = one
// A-fragment tile. Warp per dst node; single edge pass; free z. If mkfrag,
// the new h rows are converted to bf16 fragments in-block (replaces convA).
__global__ void __launch_bounds__(512, 2)
gat_fused_k(const float* __restrict__ bias, int n, int l, int mkfrag) {
    __shared__ float sh_a[16][128];
    __shared__ float hs[16][132];
    int tid = threadIdx.x;
    int w = tid >> 5;
    int lane = tid & 31;
    int node = blockIdx.x * 16 + w;
    int head = lane >> 3;
    bool valid = node < n;
    float4 y = make_float4(0.f, 0.f, 0.f, 0.f);

    if (valid) {
        int rs = (node > 0) ? d_offs[node - 1] : 0;
        int re = d_offs[node];

        float4 er4 = *(const float4*)(d_er + node * NHEADS);
        float4 em = *(const float4*)(d_elmax + l * NHEADS);
        float m[4];
        {
            float t0 = em.x + er4.x; m[0] = (t0 > 0.0f) ? t0 : 0.2f * t0;
            float t1 = em.y + er4.y; m[1] = (t1 > 0.0f) ? t1 : 0.2f * t1;
            float t2 = em.z + er4.z; m[2] = (t2 > 0.0f) ? t2 : 0.2f * t2;
            float t3 = em.w + er4.w; m[3] = (t3 > 0.0f) ? t3 : 0.2f * t3;
        }

        float z = 0.0f;
        float4 acc = make_float4(0.0f, 0.0f, 0.0f, 0.0f);
        for (int base = rs; base < re; base += 32) {
            int i = base + lane;
            int s_reg = 0;
            float4 a4 = make_float4(0.0f, 0.0f, 0.0f, 0.0f);
            if (i < re) {
                s_reg = d_esrc[i];
                float4 el4 = *(const float4*)(d_el + s_reg * NHEADS);
                float v0 = el4.x + er4.x; v0 = (v0 > 0.0f) ? v0 : 0.2f * v0;
                float v1 = el4.y + er4.y; v1 = (v1 > 0.0f) ? v1 : 0.2f * v1;
                float v2 = el4.z + er4.z; v2 = (v2 > 0.0f) ? v2 : 0.2f * v2;
                float v3 = el4.w + er4.w; v3 = (v3 > 0.0f) ? v3 : 0.2f * v3;
                a4.x = __expf(v0 - m[0]); a4.y = __expf(v1 - m[1]);
                a4.z = __expf(v2 - m[2]); a4.w = __expf(v3 - m[3]);
            }
            *(float4*)&sh_a[w][lane * 4] = a4;
            __syncwarp();
            int cnt = min(32, re - base);
            #pragma unroll 4
            for (int j = 0; j < cnt; j++) {
                int s = __shfl_sync(0xffffffffu, s_reg, j);
                float a = sh_a[w][j * 4 + head];
                z += a;
                float4 f = *(const float4*)(d_feat + s * HDIM + lane * 4);
                acc.x += a * f.x; acc.y += a * f.y; acc.z += a * f.z; acc.w += a * f.w;
            }
            __syncwarp();
        }
        float rz = (z > 0.0f) ? (1.0f / z) : 0.0f;

        float4 hv = *(const float4*)(d_h + node * HDIM + lane * 4);
        float4 bv = *(const float4*)(bias + lane * 4);
        y.x = fmaxf(acc.x * rz + hv.x + bv.x, 0.0f);
        y.y = fmaxf(acc.y * rz + hv.y + bv.y, 0.0f);
        y.z = fmaxf(acc.z * rz + hv.z + bv.z, 0.0f);
        y.w = fmaxf(acc.w * rz + hv.w + bv.w, 0.0f);
        *(float4*)(d_h + node * HDIM + lane * 4) = y;
    }

    if (mkfrag) {
        *(float4*)&hs[w][lane * 4] = y;    // zeros for invalid rows
        __syncthreads();
        if (tid < 256) {
            int ch = tid >> 5;
            int fl = tid & 31;
            int fg = fl >> 2, ft4 = fl & 3;
            int kb = ch * 16;
            unsigned int h0, l0_, h1, l1_, h2, l2_, h3, l3_;
            bf16_split_pair(hs[fg][kb + 2 * ft4], hs[fg][kb + 2 * ft4 + 1], h0, l0_);
            bf16_split_pair(hs[fg + 8][kb + 2 * ft4], hs[fg + 8][kb + 2 * ft4 + 1], h1, l1_);
            bf16_split_pair(hs[fg][kb + 2 * ft4 + 8], hs[fg][kb + 2 * ft4 + 9], h2, l2_);
            bf16_split_pair(hs[fg + 8][kb + 2 * ft4 + 8], hs[fg + 8][kb + 2 * ft4 + 9], h3, l3_);
            unsigned int* p = &d_Afrag[(((unsigned)blockIdx.x * 8 + ch) * 32 + fl) * 8];
            *(uint4*)p = make_uint4(h0, h1, h2, h3);
            *(uint4*)(p + 4) = make_uint4(l0_, l1_, l2_, l3_);
        }
    }
}

// Fused LayerNorm + gate + pooling accumulation (shift-0 exp: LN bounds gate).
__global__ void ln_gate_pool_k(const float* __restrict__ gamma, const float* __restrict__ beta,
                               const float* __restrict__ gw, const float* __restrict__ gb,
                               const int* __restrict__ gid, int n) {
    int t = blockIdx.x * blockDim.x + threadIdx.x;
    int node = t >> 5;
    if (node >= n) return;
    int lane = t & 31;
    float4 x = *(const float4*)(d_h + node * HDIM + lane * 4);
    float s = x.x + x.y + x.z + x.w;
    float sq = x.x * x.x + x.y * x.y + x.z * x.z + x.w * x.w;
    s = warpSum(s);
    sq = warpSum(sq);
    float mu = s * (1.0f / HDIM);
    float var = sq * (1.0f / HDIM) - mu * mu;
    float inv = rsqrtf(var + 1e-5f);
    float4 g = *(const float4*)(gamma + lane * 4);
    float4 b = *(const float4*)(beta + lane * 4);
    float4 y;
    y.x = (x.x - mu) * inv * g.x + b.x;
    y.y = (x.y - mu) * inv * g.y + b.y;
    y.z = (x.z - mu) * inv * g.z + b.z;
    y.w = (x.w - mu) * inv * g.w + b.w;
    float4 w = *(const float4*)(gw + lane * 4);
    float gp = y.x * w.x + y.y * w.y + y.z * w.z + y.w * w.w;
    gp = warpSum(gp);
    float p = __expf(gp + gb[0]);
    int gr = gid[node];
    if (lane == 0) atomicAdd(&d_gz[gr], p);
    redAdd4(d_zg + gr * HDIM + lane * 4, p * y.x, p * y.y, p * y.z, p * y.w);
}

// out = relu((zg/gz) @ W1 + b1) @ W2 + b2, one block per graph
__global__ void final_k(const float* __restrict__ W1, const float* __restrict__ b1,
                        const float* __restrict__ W2, const float* __restrict__ b2,
                        float* __restrict__ out) {
    __shared__ float row[HDIM];
    __shared__ float z1[HDIM];
    int g = blockIdx.x;
    int t = threadIdx.x;
    float gz = d_gz[g];
    float inv = (gz > 0.0f) ? (1.0f / gz) : 0.0f;
    row[t] = d_zg[g * HDIM + t] * inv;
    __syncthreads();
    float acc = b1[t];
    #pragma unroll 8
    for (int k = 0; k < HDIM; k++) acc += row[k] * W1[k * HDIM + t];
    z1[t] = (acc > 0.0f) ? acc : 0.0f;
    __syncthreads();
    if (t < 64) {
        float a2 = b2[t];
        #pragma unroll 8
        for (int k = 0; k < HDIM; k++) a2 += z1[k] * W2[k * 64 + t];
        out[g * 64 + t] = a2;
    }
}

// ---------------- launch ----------------
extern "C" void kernel_launch(void* const* d_in, const int* in_sizes, int n_in,
                              void* d_out, int out_size) {
    const int*   gt    = (const int*)d_in[0];
    const int*   qi    = (const int*)d_in[1];
    const int*   src   = (const int*)d_in[2];
    const int*   dst   = (const int*)d_in[3];
    const int*   gid   = (const int*)d_in[4];
    const float* ge    = (const float*)d_in[5];
    const float* qe    = (const float*)d_in[6];
    const float* W     = (const float*)d_in[7];
    const float* al    = (const float*)d_in[8];
    const float* ar    = (const float*)d_in[9];
    const float* bias  = (const float*)d_in[10];
    const float* gamma = (const float*)d_in[11];
    const float* beta  = (const float*)d_in[12];
    const float* gw    = (const float*)d_in[13];
    const float* gb    = (const float*)d_in[14];
    const float* W1    = (const float*)d_in[15];
    const float* b1    = (const float*)d_in[16];
    const float* W2    = (const float*)d_in[17];
    const float* b2    = (const float*)d_in[18];

    int n = in_sizes[0];
    int e = in_sizes[2];

    const int T = 256;
    int ntiles = (n + 15) / 16;
    int gConvA = (n + 127) / 128;
    int gGemm  = (ntiles + 3) / 4;
    int gGat   = (n + 15) / 16;
    int gEdge  = (e + T - 1) / T;
    int gNode  = (n + T - 1) / T;
    int nb     = (n + 1023) / 1024;

    csr_zero_k<<<gNode, T>>>(n);                                   // 1
    convB_k<<<(3 * 128 * 32 + T - 1) / T, T>>>(W);                 // 2
    convA_k<<<gConvA, 256>>>(n, gt, qi, ge, qe);                   // 3 (embed + frag)
    gemm_attn_k<<<gGemm, 256>>>(al, ar, n, 0, ntiles);             // 4 (profiled)
    csr_hist_k<<<gEdge, T>>>(dst, e);                              // 5
    csr_scan1_k<<<nb, 1024>>>(n);                                  // 6
    csr_scan2_k<<<1, 32>>>(nb, n);                                 // 7
    csr_scan3_k<<<nb, 1024>>>(n);                                  // 8
    csr_scatter_k<<<gEdge, T>>>(src, dst, e);                      // 9
    gat_fused_k<<<gGat, 512>>>(bias, n, 0, 1);                     // 10 (frags for l=1)

    gemm_attn_k<<<gGemm, 256>>>(al + HDIM, ar + HDIM, n, 1, ntiles);
    gat_fused_k<<<gGat, 512>>>(bias + HDIM, n, 1, 1);              // frags for l=2
    gemm_attn_k<<<gGemm, 256>>>(al + 2 * HDIM, ar + 2 * HDIM, n, 2, ntiles);
    gat_fused_k<<<gGat, 512>>>(bias + 2 * HDIM, n, 2, 0);

    ln_gate_pool_k<<<(n * 32 + T - 1) / T, T>>>(gamma, beta, gw, gb, gid, n);
    final_k<<<GMAX, HDIM>>>(W1, b1, W2, b2, (float*)d_out);
}